// round 14
// baseline (speedup 1.0000x reference)
#include <cuda_runtime.h>
#include <cuda_fp16.h>
#include <cstdint>
#include <cstddef>

#define B_  32
#define S_  512
#define H_  768
#define NH_ 12
#define DH_ 64
#define M_  (B_*S_)       // 16384
#define XN  ((size_t)M_*H_)
#define WN  ((size_t)H_*H_)

// fp16 copies of inputs
__device__ __half g_xh[XN];
__device__ __half g_wh[3*WN];
// Head-split scratch, fp16: [b][h][s][d]. g_q pre-scaled by 0.125*log2(e).
__device__ __half g_q[XN];
__device__ __half g_k[XN];
__device__ __half g_v[XN];

#define QSCALE 0.18033688011112042f   // 0.125 * log2(e)
#define ONES_H2 0x3C003C00u           // half2(1.0, 1.0)

__device__ __forceinline__ void mma_f16(float* c, const uint32_t* a, const uint32_t* b) {
    asm volatile(
        "mma.sync.aligned.m16n8k16.row.col.f32.f16.f16.f32 "
        "{%0,%1,%2,%3}, {%4,%5,%6,%7}, {%8,%9}, {%0,%1,%2,%3};\n"
        : "+f"(c[0]), "+f"(c[1]), "+f"(c[2]), "+f"(c[3])
        : "r"(a[0]), "r"(a[1]), "r"(a[2]), "r"(a[3]), "r"(b[0]), "r"(b[1]));
}
__device__ __forceinline__ uint32_t h2(float x, float y) {
    __half2 h = __floats2half2_rn(x, y);
    return *(uint32_t*)&h;
}
// exp2 of a float pair, computed in f16x2 (1 cvt + 1 MUFU for 2 elements)
__device__ __forceinline__ uint32_t ex2h2(float x, float y) {
    uint32_t p = h2(x, y), r;
    asm("ex2.approx.f16x2 %0, %1;" : "=r"(r) : "r"(p));
    return r;
}
__device__ __forceinline__ uint32_t smem_u32(const void* p) {
    return (uint32_t)__cvta_generic_to_shared(p);
}
__device__ __forceinline__ void ldmx4(uint32_t* r, uint32_t addr) {
    asm volatile("ldmatrix.sync.aligned.m8n8.x4.shared.b16 {%0,%1,%2,%3}, [%4];"
        : "=r"(r[0]), "=r"(r[1]), "=r"(r[2]), "=r"(r[3]) : "r"(addr));
}
__device__ __forceinline__ void ldmx4t(uint32_t* r, uint32_t addr) {
    asm volatile("ldmatrix.sync.aligned.m8n8.x4.trans.shared.b16 {%0,%1,%2,%3}, [%4];"
        : "=r"(r[0]), "=r"(r[1]), "=r"(r[2]), "=r"(r[3]) : "r"(addr));
}
__device__ __forceinline__ void cpasync16(uint32_t dst, const void* src) {
    asm volatile("cp.async.cg.shared.global [%0], [%1], 16;" :: "r"(dst), "l"(src));
}
__device__ __forceinline__ void cpasync_commit() {
    asm volatile("cp.async.commit_group;");
}

// ---------------------------------------------------------------------------
// fp32 -> fp16 conversion of x, Wq, Wk, Wv. 16 elems/thread, MLP=4.
// ---------------------------------------------------------------------------
__global__ __launch_bounds__(256) void cvt_fp16(
    const float* __restrict__ x,  const float* __restrict__ Wq,
    const float* __restrict__ Wk, const float* __restrict__ Wv)
{
    size_t i = ((size_t)blockIdx.x * 256 + threadIdx.x) * 16;
    const float* src;
    __half* dst;
    if (i < XN) { src = x + i; dst = g_xh + i; }
    else {
        size_t j = i - XN;
        size_t which = j / WN;
        src = ((which == 0) ? Wq : (which == 1) ? Wk : Wv) + (j - which * WN);
        dst = g_wh + j;
    }
    float4 f[4];
    #pragma unroll
    for (int t = 0; t < 4; t++) f[t] = *(const float4*)(src + t * 4);
    uint32_t o[8];
    #pragma unroll
    for (int t = 0; t < 4; t++) {
        o[2*t]   = h2(f[t].x, f[t].y);
        o[2*t+1] = h2(f[t].z, f[t].w);
    }
    *(uint4*)dst       = *(uint4*)(o + 0);
    *(uint4*)(dst + 8) = *(uint4*)(o + 4);
}

// ---------------------------------------------------------------------------
// QKV GEMM (unchanged, best-known): fp16, 3-stage cp.async ring, XOR-swizzled
// smem, one sync per slab, deferred cp.async issue after ks=0.
// BM=BN=128, BK=64, 256 thr, warps 4(M)x2(N), 2 CTAs/SM.
// ---------------------------------------------------------------------------
#define GROW 64
#define GEMM_SMEM (6 * 128 * GROW * 2)   // 98304 B (3 stages x A,B)

__global__ __launch_bounds__(256, 2) void qkv_fp16(
    const float* __restrict__ bq, const float* __restrict__ bk,
    const float* __restrict__ bv)
{
    extern __shared__ __half smem[];

    const int which = blockIdx.z;
    const float* bias = (which == 0) ? bq : (which == 1) ? bk : bv;
    __half* out       = (which == 0) ? g_q : (which == 1) ? g_k : g_v;
    const __half* Wh  = g_wh + (size_t)which * WN;

    const int tid = threadIdx.x, lane = tid & 31, warp = tid >> 5;
    const int wm = warp >> 1, wn = warp & 1;
    const int gid = lane >> 2, tig = lane & 3;
    const int m0 = blockIdx.y * 128, n0 = blockIdx.x * 128;

    const int a_r = ((lane >> 3) & 1) * 8 + (lane & 7);
    const int a_ch = lane >> 4;
    const int b_r = lane & 7;
    const int b_j = lane >> 4;
    const int b_ch = (lane >> 3) & 1;

    int crow[4], cch[4];
    #pragma unroll
    for (int t = 0; t < 4; t++) {
        int idx = tid + t * 256;
        crow[t] = idx >> 3;
        cch[t]  = idx & 7;
    }

    auto issue = [&](int slab, int buf) {
        const int k0 = slab * 64;
        __half* dA = smem + (size_t)buf * 128 * GROW;
        __half* dB = smem + (size_t)(3 + buf) * 128 * GROW;
        #pragma unroll
        for (int t = 0; t < 4; t++) {
            int sw = (cch[t] ^ (crow[t] & 7)) * 8;
            cpasync16(smem_u32(&dA[crow[t] * GROW + sw]),
                      &g_xh[(size_t)(m0 + crow[t]) * H_ + k0 + cch[t] * 8]);
            cpasync16(smem_u32(&dB[crow[t] * GROW + sw]),
                      &Wh[(size_t)(n0 + crow[t]) * H_ + k0 + cch[t] * 8]);
        }
        cpasync_commit();
    };

    float c[2][8][4] = {};

    issue(0, 0);
    issue(1, 1);

    #pragma unroll 1
    for (int ot = 0; ot < 4; ot++) {
        #pragma unroll
        for (int sub = 0; sub < 3; sub++) {
            const int it = ot * 3 + sub;
            if (it < 11) asm volatile("cp.async.wait_group 1;");
            else         asm volatile("cp.async.wait_group 0;");
            __syncthreads();

            const __half* cA = smem + (size_t)sub * 128 * GROW;
            const __half* cB = smem + (size_t)(3 + sub) * 128 * GROW;

            #pragma unroll
            for (int ks = 0; ks < 4; ks++) {
                uint32_t af[2][4];
                #pragma unroll
                for (int mt = 0; mt < 2; mt++) {
                    int r = wm * 32 + mt * 16 + a_r;
                    int ch = ks * 2 + a_ch;
                    ldmx4(af[mt], smem_u32(&cA[r * GROW + ((ch ^ (r & 7)) << 3)]));
                }
                uint32_t bf[8][2];
                #pragma unroll
                for (int j = 0; j < 8; j += 2) {
                    int r = wn * 64 + (j + b_j) * 8 + b_r;
                    int ch = ks * 2 + b_ch;
                    uint32_t t[4];
                    ldmx4(t, smem_u32(&cB[r * GROW + ((ch ^ (r & 7)) << 3)]));
                    bf[j][0] = t[0]; bf[j][1] = t[1];
                    bf[j+1][0] = t[2]; bf[j+1][1] = t[3];
                }
                #pragma unroll
                for (int mt = 0; mt < 2; mt++)
                    #pragma unroll
                    for (int j = 0; j < 8; j++)
                        mma_f16(c[mt][j], af[mt], bf[j]);

                // deferred cp.async issue: after the ks=0 ldmatrix burst, the
                // LSU is free while the MMA-heavy ks=1..3 phase runs.
                if (ks == 0 && it + 2 < 12) issue(it + 2, (sub + 2) % 3);
            }
        }
    }

    // epilogue: bias, scale (q: 0.125*log2e), cvt half, head-split store
    const float scale = (which == 0) ? QSCALE : 1.0f;
    #pragma unroll
    for (int mt = 0; mt < 2; mt++)
        #pragma unroll
        for (int j = 0; j < 8; j++) {
            int ncol = n0 + wn * 64 + j * 8 + 2 * tig;
            int h = ncol >> 6, d = ncol & 63;
            float bs0 = bias[ncol], bs1 = bias[ncol + 1];
            #pragma unroll
            for (int hf = 0; hf < 2; hf++) {
                int rowg = m0 + wm * 32 + mt * 16 + gid + hf * 8;
                int b = rowg >> 9, s = rowg & 511;
                __half2* dst = (__half2*)&out[(((size_t)b * NH_ + h) * S_ + s) * DH_ + d];
                *dst = __floats2half2_rn((c[mt][j][hf*2+0] + bs0) * scale,
                                         (c[mt][j][hf*2+1] + bs1) * scale);
            }
        }
}

// ---------------------------------------------------------------------------
// Flash attention: fp16 HMMA, 256 thr = 8 warps, 128 queries/block,
// 128-key staged tiles (two 64-key subtiles, no barrier between).
// exp fused INTO the PV loop: per-ks ex2.approx.f16x2 interleaves MUFU with
// tensor issue and removes the plo/phi[8] register arrays (16 regs freed).
// Row sums via ones-column MMA. S-phase ks-outer, batched fragment loads.
// ---------------------------------------------------------------------------
#define AKS 72
#define ATTN_SMEM (5 * 128 * AKS * 2)   // Q + 2xK(128) + 2xV(128) = 92160 B

__global__ __launch_bounds__(256, 2) void attn_flash(float* __restrict__ out)
{
    extern __shared__ __half asm_[];
    __half* Qs    = asm_;
    __half* Kb[2] = { asm_ + 128*AKS,  asm_ + 2*128*AKS };
    __half* Vb[2] = { asm_ + 3*128*AKS, asm_ + 4*128*AKS };

    const int tid = threadIdx.x, lane = tid & 31, warp = tid >> 5;
    const int gid = lane >> 2, tig = lane & 3;
    const int qt = blockIdx.x, bh = blockIdx.y;
    const int s0 = qt * 128;
    const size_t base = (size_t)bh * S_ * DH_;

    int crow[4], cdg[4];
    #pragma unroll
    for (int t = 0; t < 4; t++) {
        int idx = tid + t * 256;
        crow[t] = idx >> 3;
        cdg[t]  = (idx & 7) * 8;
    }

    auto stage_kv = [&](int ktile, int buf) {
        const size_t gb = base + (size_t)ktile * 128 * DH_;
        #pragma unroll
        for (int t = 0; t < 4; t++) {
            cpasync16(smem_u32(&Kb[buf][crow[t] * AKS + cdg[t]]),
                      &g_k[gb + (size_t)crow[t] * DH_ + cdg[t]]);
            cpasync16(smem_u32(&Vb[buf][crow[t] * AKS + cdg[t]]),
                      &g_v[gb + (size_t)crow[t] * DH_ + cdg[t]]);
        }
        cpasync_commit();
    };

    #pragma unroll
    for (int t = 0; t < 4; t++) {
        cpasync16(smem_u32(&Qs[crow[t] * AKS + cdg[t]]),
                  &g_q[base + (size_t)(s0 + crow[t]) * DH_ + cdg[t]]);
    }
    stage_kv(0, 0);
    asm volatile("cp.async.wait_group 0;");
    __syncthreads();

    const int a_r = ((lane >> 3) & 1) * 8 + (lane & 7);
    const int a_c = (lane >> 4) * 8;
    const int k_r = lane & 7;
    const int k_j = lane >> 4;
    const int k_c = ((lane >> 3) & 1) * 8;
    const int v_r = ((lane >> 3) & 1) * 8 + (lane & 7);
    const int v_j = lane >> 4;

    uint32_t qa[4][4];
    #pragma unroll
    for (int ks = 0; ks < 4; ks++)
        ldmx4(qa[ks], smem_u32(&Qs[(warp * 16 + a_r) * AKS + ks * 16 + a_c]));

    float oc[8][4] = {};
    float lsum[4] = {};                   // ones-MMA row-sum accumulator
    const uint32_t ones[2] = { ONES_H2, ONES_H2 };

    #pragma unroll 1
    for (int kt = 0; kt < 4; kt++) {
        #pragma unroll
        for (int half = 0; half < 2; half++) {
            const __half* cK = Kb[kt & 1] + half * 64 * AKS;
            const __half* cV = Vb[kt & 1] + half * 64 * AKS;

            // ---- S(log2) = Q K^T : ks OUTER, batched K-fragment loads ----
            float sc[8][4] = {};
            #pragma unroll
            for (int ks = 0; ks < 4; ks++) {
                uint32_t kb[4][4];
                #pragma unroll
                for (int jp = 0; jp < 4; jp++)
                    ldmx4(kb[jp],
                        smem_u32(&cK[((2*jp + k_j) * 8 + k_r) * AKS + ks * 16 + k_c]));
                #pragma unroll
                for (int jp = 0; jp < 4; jp++) {
                    mma_f16(sc[2*jp],     qa[ks], kb[jp] + 0);
                    mma_f16(sc[2*jp + 1], qa[ks], kb[jp] + 2);
                }
            }

            // deferred next-tile staging: after the K-ldmatrix bursts, the LSU
            // is free while exp + P@V (MMA-heavy) run.
            if (half == 0 && kt < 3) stage_kv(kt + 1, (kt + 1) & 1);

            // ---- fused exp + PV: per-ks ex2 (MUFU) interleaved with MMAs ----
            #pragma unroll
            for (int ks = 0; ks < 4; ks++) {
                uint32_t pf[4];
                pf[0] = ex2h2(sc[2*ks][0],   sc[2*ks][1]);
                pf[1] = ex2h2(sc[2*ks][2],   sc[2*ks][3]);
                pf[2] = ex2h2(sc[2*ks+1][0], sc[2*ks+1][1]);
                pf[3] = ex2h2(sc[2*ks+1][2], sc[2*ks+1][3]);
                uint32_t vb[4][4];
                #pragma unroll
                for (int jp = 0; jp < 4; jp++)
                    ldmx4t(vb[jp],
                        smem_u32(&cV[(ks * 16 + v_r) * AKS + (2*jp + v_j) * 8]));
                mma_f16(lsum, pf, ones);
                #pragma unroll
                for (int jp = 0; jp < 4; jp++) {
                    mma_f16(oc[2*jp],     pf, vb[jp] + 0);
                    mma_f16(oc[2*jp + 1], pf, vb[jp] + 2);
                }
            }
        }

        if (kt < 3) {
            asm volatile("cp.async.wait_group 0;");
            __syncthreads();
        }
    }

    const float inv0 = 1.0f / lsum[0];   // row gid   (replicated over columns)
    const float inv1 = 1.0f / lsum[2];   // row gid+8

    const int b = bh / NH_, h = bh % NH_;
    const int s_lo = s0 + warp * 16 + gid;
    #pragma unroll
    for (int j = 0; j < 8; j++) {
        int d = j * 8 + 2 * tig;
        float2 o0 = make_float2(tanhf(oc[j][0] * inv0), tanhf(oc[j][1] * inv0));
        float2 o1 = make_float2(tanhf(oc[j][2] * inv1), tanhf(oc[j][3] * inv1));
        *(float2*)&out[((size_t)(b * S_ + s_lo)) * H_ + h * DH_ + d] = o0;
        *(float2*)&out[((size_t)(b * S_ + s_lo + 8)) * H_ + h * DH_ + d] = o1;
    }
}

// ---------------------------------------------------------------------------
extern "C" void kernel_launch(void* const* d_in, const int* in_sizes, int n_in,
                              void* d_out, int out_size)
{
    const float* x  = (const float*)d_in[0];
    const float* Wq = (const float*)d_in[1];
    const float* bq = (const float*)d_in[2];
    const float* Wk = (const float*)d_in[3];
    const float* bk = (const float*)d_in[4];
    const float* Wv = (const float*)d_in[5];
    const float* bv = (const float*)d_in[6];
    float* out = (float*)d_out;

    cudaFuncSetAttribute(qkv_fp16,
                         cudaFuncAttributeMaxDynamicSharedMemorySize, GEMM_SMEM);
    cudaFuncSetAttribute(attn_flash,
                         cudaFuncAttributeMaxDynamicSharedMemorySize, ATTN_SMEM);

    const int cvt_blocks = (int)((XN + 3 * WN) / (256 * 16));   // 3504
    cvt_fp16<<<cvt_blocks, 256>>>(x, Wq, Wk, Wv);

    dim3 ggrid(H_ / 128, M_ / 128, 3);   // (6, 128, 3)
    qkv_fp16<<<ggrid, 256, GEMM_SMEM>>>(bq, bk, bv);

    dim3 agrid(S_ / 128, B_ * NH_);      // (4, 384)
    attn_flash<<<agrid, 256, ATTN_SMEM>>>(out);
}

// round 15
// speedup vs baseline: 1.0222x; 1.0222x over previous
#include <cuda_runtime.h>
#include <cuda_fp16.h>
#include <cstdint>
#include <cstddef>

#define B_  32
#define S_  512
#define H_  768
#define NH_ 12
#define DH_ 64
#define M_  (B_*S_)       // 16384
#define XN  ((size_t)M_*H_)
#define WN  ((size_t)H_*H_)

// fp16 copies of inputs
__device__ __half g_xh[XN];
__device__ __half g_wh[3*WN];
// Head-split scratch, fp16: [b][h][s][d]. g_q pre-scaled by 0.125*log2(e).
__device__ __half g_q[XN];
__device__ __half g_k[XN];
__device__ __half g_v[XN];

#define QSCALE 0.18033688011112042f   // 0.125 * log2(e)
#define ONES_H2 0x3C003C00u           // half2(1.0, 1.0)

__device__ __forceinline__ void mma_f16(float* c, const uint32_t* a, const uint32_t* b) {
    asm volatile(
        "mma.sync.aligned.m16n8k16.row.col.f32.f16.f16.f32 "
        "{%0,%1,%2,%3}, {%4,%5,%6,%7}, {%8,%9}, {%0,%1,%2,%3};\n"
        : "+f"(c[0]), "+f"(c[1]), "+f"(c[2]), "+f"(c[3])
        : "r"(a[0]), "r"(a[1]), "r"(a[2]), "r"(a[3]), "r"(b[0]), "r"(b[1]));
}
__device__ __forceinline__ uint32_t h2(float x, float y) {
    __half2 h = __floats2half2_rn(x, y);
    return *(uint32_t*)&h;
}
// exp2 of a float pair, computed in f16x2 (1 cvt + 1 MUFU for 2 elements)
__device__ __forceinline__ uint32_t ex2h2(float x, float y) {
    uint32_t p = h2(x, y), r;
    asm("ex2.approx.f16x2 %0, %1;" : "=r"(r) : "r"(p));
    return r;
}
// hardware tanh (MUFU), final-output use only
__device__ __forceinline__ float tanh_ap(float x) {
    float r; asm("tanh.approx.f32 %0, %1;" : "=f"(r) : "f"(x)); return r;
}
__device__ __forceinline__ uint32_t smem_u32(const void* p) {
    return (uint32_t)__cvta_generic_to_shared(p);
}
__device__ __forceinline__ void ldmx4(uint32_t* r, uint32_t addr) {
    asm volatile("ldmatrix.sync.aligned.m8n8.x4.shared.b16 {%0,%1,%2,%3}, [%4];"
        : "=r"(r[0]), "=r"(r[1]), "=r"(r[2]), "=r"(r[3]) : "r"(addr));
}
__device__ __forceinline__ void ldmx4t(uint32_t* r, uint32_t addr) {
    asm volatile("ldmatrix.sync.aligned.m8n8.x4.trans.shared.b16 {%0,%1,%2,%3}, [%4];"
        : "=r"(r[0]), "=r"(r[1]), "=r"(r[2]), "=r"(r[3]) : "r"(addr));
}
__device__ __forceinline__ void cpasync16(uint32_t dst, const void* src) {
    asm volatile("cp.async.cg.shared.global [%0], [%1], 16;" :: "r"(dst), "l"(src));
}
__device__ __forceinline__ void cpasync_commit() {
    asm volatile("cp.async.commit_group;");
}

// ---------------------------------------------------------------------------
// fp32 -> fp16 conversion of x, Wq, Wk, Wv (8 elems/thread — best-known)
// ---------------------------------------------------------------------------
__global__ __launch_bounds__(256) void cvt_fp16(
    const float* __restrict__ x,  const float* __restrict__ Wq,
    const float* __restrict__ Wk, const float* __restrict__ Wv)
{
    size_t i = ((size_t)blockIdx.x * 256 + threadIdx.x) * 8;
    const float* src;
    __half* dst;
    if (i < XN) { src = x + i; dst = g_xh + i; }
    else {
        size_t j = i - XN;
        size_t which = j / WN;
        src = ((which == 0) ? Wq : (which == 1) ? Wk : Wv) + (j - which * WN);
        dst = g_wh + j;
    }
    float4 f0 = *(const float4*)src;
    float4 f1 = *(const float4*)(src + 4);
    uint32_t o[4];
    o[0] = h2(f0.x, f0.y); o[1] = h2(f0.z, f0.w);
    o[2] = h2(f1.x, f1.y); o[3] = h2(f1.z, f1.w);
    *(uint4*)dst = *(uint4*)o;
}

// ---------------------------------------------------------------------------
// QKV GEMM (best-known): fp16, 3-stage cp.async ring, XOR-swizzled smem,
// one sync per slab, deferred cp.async issue after ks=0.
// BM=BN=128, BK=64, 256 thr, warps 4(M)x2(N), 2 CTAs/SM.
// ---------------------------------------------------------------------------
#define GROW 64
#define GEMM_SMEM (6 * 128 * GROW * 2)   // 98304 B (3 stages x A,B)

__global__ __launch_bounds__(256, 2) void qkv_fp16(
    const float* __restrict__ bq, const float* __restrict__ bk,
    const float* __restrict__ bv)
{
    extern __shared__ __half smem[];

    const int which = blockIdx.z;
    const float* bias = (which == 0) ? bq : (which == 1) ? bk : bv;
    __half* out       = (which == 0) ? g_q : (which == 1) ? g_k : g_v;
    const __half* Wh  = g_wh + (size_t)which * WN;

    const int tid = threadIdx.x, lane = tid & 31, warp = tid >> 5;
    const int wm = warp >> 1, wn = warp & 1;
    const int gid = lane >> 2, tig = lane & 3;
    const int m0 = blockIdx.y * 128, n0 = blockIdx.x * 128;

    const int a_r = ((lane >> 3) & 1) * 8 + (lane & 7);
    const int a_ch = lane >> 4;
    const int b_r = lane & 7;
    const int b_j = lane >> 4;
    const int b_ch = (lane >> 3) & 1;

    int crow[4], cch[4];
    #pragma unroll
    for (int t = 0; t < 4; t++) {
        int idx = tid + t * 256;
        crow[t] = idx >> 3;
        cch[t]  = idx & 7;
    }

    auto issue = [&](int slab, int buf) {
        const int k0 = slab * 64;
        __half* dA = smem + (size_t)buf * 128 * GROW;
        __half* dB = smem + (size_t)(3 + buf) * 128 * GROW;
        #pragma unroll
        for (int t = 0; t < 4; t++) {
            int sw = (cch[t] ^ (crow[t] & 7)) * 8;
            cpasync16(smem_u32(&dA[crow[t] * GROW + sw]),
                      &g_xh[(size_t)(m0 + crow[t]) * H_ + k0 + cch[t] * 8]);
            cpasync16(smem_u32(&dB[crow[t] * GROW + sw]),
                      &Wh[(size_t)(n0 + crow[t]) * H_ + k0 + cch[t] * 8]);
        }
        cpasync_commit();
    };

    float c[2][8][4] = {};

    issue(0, 0);
    issue(1, 1);

    #pragma unroll 1
    for (int ot = 0; ot < 4; ot++) {
        #pragma unroll
        for (int sub = 0; sub < 3; sub++) {
            const int it = ot * 3 + sub;
            if (it < 11) asm volatile("cp.async.wait_group 1;");
            else         asm volatile("cp.async.wait_group 0;");
            __syncthreads();

            const __half* cA = smem + (size_t)sub * 128 * GROW;
            const __half* cB = smem + (size_t)(3 + sub) * 128 * GROW;

            #pragma unroll
            for (int ks = 0; ks < 4; ks++) {
                uint32_t af[2][4];
                #pragma unroll
                for (int mt = 0; mt < 2; mt++) {
                    int r = wm * 32 + mt * 16 + a_r;
                    int ch = ks * 2 + a_ch;
                    ldmx4(af[mt], smem_u32(&cA[r * GROW + ((ch ^ (r & 7)) << 3)]));
                }
                uint32_t bf[8][2];
                #pragma unroll
                for (int j = 0; j < 8; j += 2) {
                    int r = wn * 64 + (j + b_j) * 8 + b_r;
                    int ch = ks * 2 + b_ch;
                    uint32_t t[4];
                    ldmx4(t, smem_u32(&cB[r * GROW + ((ch ^ (r & 7)) << 3)]));
                    bf[j][0] = t[0]; bf[j][1] = t[1];
                    bf[j+1][0] = t[2]; bf[j+1][1] = t[3];
                }
                #pragma unroll
                for (int mt = 0; mt < 2; mt++)
                    #pragma unroll
                    for (int j = 0; j < 8; j++)
                        mma_f16(c[mt][j], af[mt], bf[j]);

                // deferred cp.async issue: after the ks=0 ldmatrix burst, the
                // LSU is free while the MMA-heavy ks=1..3 phase runs.
                if (ks == 0 && it + 2 < 12) issue(it + 2, (sub + 2) % 3);
            }
        }
    }

    // epilogue: bias, scale (q: 0.125*log2e), cvt half, head-split store
    const float scale = (which == 0) ? QSCALE : 1.0f;
    #pragma unroll
    for (int mt = 0; mt < 2; mt++)
        #pragma unroll
        for (int j = 0; j < 8; j++) {
            int ncol = n0 + wn * 64 + j * 8 + 2 * tig;
            int h = ncol >> 6, d = ncol & 63;
            float bs0 = bias[ncol], bs1 = bias[ncol + 1];
            #pragma unroll
            for (int hf = 0; hf < 2; hf++) {
                int rowg = m0 + wm * 32 + mt * 16 + gid + hf * 8;
                int b = rowg >> 9, s = rowg & 511;
                __half2* dst = (__half2*)&out[(((size_t)b * NH_ + h) * S_ + s) * DH_ + d];
                *dst = __floats2half2_rn((c[mt][j][hf*2+0] + bs0) * scale,
                                         (c[mt][j][hf*2+1] + bs1) * scale);
            }
        }
}

// ---------------------------------------------------------------------------
// Flash attention (best-known): fp16 HMMA, 256 thr = 8 warps, 128 q/block,
// 128-key staged tiles (two 64-key subtiles, no barrier between).
// S-phase ks-outer with batched fragment loads; SEPARATE exp block
// (ex2.approx.f16x2); row sums via ones-column MMA; tanh.approx epilogue.
// ---------------------------------------------------------------------------
#define AKS 72
#define ATTN_SMEM (5 * 128 * AKS * 2)   // Q + 2xK(128) + 2xV(128) = 92160 B

__global__ __launch_bounds__(256, 2) void attn_flash(float* __restrict__ out)
{
    extern __shared__ __half asm_[];
    __half* Qs    = asm_;
    __half* Kb[2] = { asm_ + 128*AKS,  asm_ + 2*128*AKS };
    __half* Vb[2] = { asm_ + 3*128*AKS, asm_ + 4*128*AKS };

    const int tid = threadIdx.x, lane = tid & 31, warp = tid >> 5;
    const int gid = lane >> 2, tig = lane & 3;
    const int qt = blockIdx.x, bh = blockIdx.y;
    const int s0 = qt * 128;
    const size_t base = (size_t)bh * S_ * DH_;

    int crow[4], cdg[4];
    #pragma unroll
    for (int t = 0; t < 4; t++) {
        int idx = tid + t * 256;
        crow[t] = idx >> 3;
        cdg[t]  = (idx & 7) * 8;
    }

    auto stage_kv = [&](int ktile, int buf) {
        const size_t gb = base + (size_t)ktile * 128 * DH_;
        #pragma unroll
        for (int t = 0; t < 4; t++) {
            cpasync16(smem_u32(&Kb[buf][crow[t] * AKS + cdg[t]]),
                      &g_k[gb + (size_t)crow[t] * DH_ + cdg[t]]);
            cpasync16(smem_u32(&Vb[buf][crow[t] * AKS + cdg[t]]),
                      &g_v[gb + (size_t)crow[t] * DH_ + cdg[t]]);
        }
        cpasync_commit();
    };

    #pragma unroll
    for (int t = 0; t < 4; t++) {
        cpasync16(smem_u32(&Qs[crow[t] * AKS + cdg[t]]),
                  &g_q[base + (size_t)(s0 + crow[t]) * DH_ + cdg[t]]);
    }
    stage_kv(0, 0);
    asm volatile("cp.async.wait_group 0;");
    __syncthreads();

    const int a_r = ((lane >> 3) & 1) * 8 + (lane & 7);
    const int a_c = (lane >> 4) * 8;
    const int k_r = lane & 7;
    const int k_j = lane >> 4;
    const int k_c = ((lane >> 3) & 1) * 8;
    const int v_r = ((lane >> 3) & 1) * 8 + (lane & 7);
    const int v_j = lane >> 4;

    uint32_t qa[4][4];
    #pragma unroll
    for (int ks = 0; ks < 4; ks++)
        ldmx4(qa[ks], smem_u32(&Qs[(warp * 16 + a_r) * AKS + ks * 16 + a_c]));

    float oc[8][4] = {};
    float lsum[4] = {};                   // ones-MMA row-sum accumulator
    const uint32_t ones[2] = { ONES_H2, ONES_H2 };

    #pragma unroll 1
    for (int kt = 0; kt < 4; kt++) {
        #pragma unroll
        for (int half = 0; half < 2; half++) {
            const __half* cK = Kb[kt & 1] + half * 64 * AKS;
            const __half* cV = Vb[kt & 1] + half * 64 * AKS;

            // ---- S(log2) = Q K^T : ks OUTER, batched K-fragment loads ----
            float sc[8][4] = {};
            #pragma unroll
            for (int ks = 0; ks < 4; ks++) {
                uint32_t kb[4][4];
                #pragma unroll
                for (int jp = 0; jp < 4; jp++)
                    ldmx4(kb[jp],
                        smem_u32(&cK[((2*jp + k_j) * 8 + k_r) * AKS + ks * 16 + k_c]));
                #pragma unroll
                for (int jp = 0; jp < 4; jp++) {
                    mma_f16(sc[2*jp],     qa[ks], kb[jp] + 0);
                    mma_f16(sc[2*jp + 1], qa[ks], kb[jp] + 2);
                }
            }

            // deferred next-tile staging: after the K-ldmatrix bursts, the LSU
            // is free while exp + P@V (MMA-heavy) run.
            if (half == 0 && kt < 3) stage_kv(kt + 1, (kt + 1) & 1);

            // ---- P = ex2(S) directly in f16x2 (separate block: max ILP) ----
            uint32_t plo[8], phi[8];
            #pragma unroll
            for (int j = 0; j < 8; j++) {
                plo[j] = ex2h2(sc[j][0], sc[j][1]);
                phi[j] = ex2h2(sc[j][2], sc[j][3]);
            }

            // ---- O += P V ; row sums += P @ 1 (batched V-fragment loads) ----
            #pragma unroll
            for (int ks = 0; ks < 4; ks++) {
                uint32_t pf[4] = { plo[2*ks], phi[2*ks], plo[2*ks+1], phi[2*ks+1] };
                uint32_t vb[4][4];
                #pragma unroll
                for (int jp = 0; jp < 4; jp++)
                    ldmx4t(vb[jp],
                        smem_u32(&cV[(ks * 16 + v_r) * AKS + (2*jp + v_j) * 8]));
                mma_f16(lsum, pf, ones);
                #pragma unroll
                for (int jp = 0; jp < 4; jp++) {
                    mma_f16(oc[2*jp],     pf, vb[jp] + 0);
                    mma_f16(oc[2*jp + 1], pf, vb[jp] + 2);
                }
            }
        }

        if (kt < 3) {
            asm volatile("cp.async.wait_group 0;");
            __syncthreads();
        }
    }

    const float inv0 = 1.0f / lsum[0];   // row gid   (replicated over columns)
    const float inv1 = 1.0f / lsum[2];   // row gid+8

    const int b = bh / NH_, h = bh % NH_;
    const int s_lo = s0 + warp * 16 + gid;
    #pragma unroll
    for (int j = 0; j < 8; j++) {
        int d = j * 8 + 2 * tig;
        float2 o0 = make_float2(tanh_ap(oc[j][0] * inv0), tanh_ap(oc[j][1] * inv0));
        float2 o1 = make_float2(tanh_ap(oc[j][2] * inv1), tanh_ap(oc[j][3] * inv1));
        *(float2*)&out[((size_t)(b * S_ + s_lo)) * H_ + h * DH_ + d] = o0;
        *(float2*)&out[((size_t)(b * S_ + s_lo + 8)) * H_ + h * DH_ + d] = o1;
    }
}

// ---------------------------------------------------------------------------
extern "C" void kernel_launch(void* const* d_in, const int* in_sizes, int n_in,
                              void* d_out, int out_size)
{
    const float* x  = (const float*)d_in[0];
    const float* Wq = (const float*)d_in[1];
    const float* bq = (const float*)d_in[2];
    const float* Wk = (const float*)d_in[3];
    const float* bk = (const float*)d_in[4];
    const float* Wv = (const float*)d_in[5];
    const float* bv = (const float*)d_in[6];
    float* out = (float*)d_out;

    cudaFuncSetAttribute(qkv_fp16,
                         cudaFuncAttributeMaxDynamicSharedMemorySize, GEMM_SMEM);
    cudaFuncSetAttribute(attn_flash,
                         cudaFuncAttributeMaxDynamicSharedMemorySize, ATTN_SMEM);

    const int cvt_blocks = (int)((XN + 3 * WN) / (256 * 8));   // 7008
    cvt_fp16<<<cvt_blocks, 256>>>(x, Wq, Wk, Wv);

    dim3 ggrid(H_ / 128, M_ / 128, 3);   // (6, 128, 3)
    qkv_fp16<<<ggrid, 256, GEMM_SMEM>>>(bq, bk, bv);

    dim3 agrid(S_ / 128, B_ * NH_);      // (4, 384)
    attn_flash<<<agrid, 256, ATTN_SMEM>>>(out);
}

// round 16
// speedup vs baseline: 1.0419x; 1.0193x over previous
#include <cuda_runtime.h>
#include <cuda_fp16.h>
#include <cstdint>
#include <cstddef>

#define B_  32
#define S_  512
#define H_  768
#define NH_ 12
#define DH_ 64
#define M_  (B_*S_)       // 16384
#define XN  ((size_t)M_*H_)
#define WN  ((size_t)H_*H_)

// fp16 copies of inputs
__device__ __half g_xh[XN];
__device__ __half g_wh[3*WN];
// Head-split scratch, fp16: [b][h][s][d]. g_q pre-scaled by 0.125*log2(e).
__device__ __half g_q[XN];
__device__ __half g_k[XN];
__device__ __half g_v[XN];

#define QSCALE 0.18033688011112042f   // 0.125 * log2(e)
#define ONES_H2 0x3C003C00u           // half2(1.0, 1.0)

__device__ __forceinline__ void mma_f16(float* c, const uint32_t* a, const uint32_t* b) {
    asm volatile(
        "mma.sync.aligned.m16n8k16.row.col.f32.f16.f16.f32 "
        "{%0,%1,%2,%3}, {%4,%5,%6,%7}, {%8,%9}, {%0,%1,%2,%3};\n"
        : "+f"(c[0]), "+f"(c[1]), "+f"(c[2]), "+f"(c[3])
        : "r"(a[0]), "r"(a[1]), "r"(a[2]), "r"(a[3]), "r"(b[0]), "r"(b[1]));
}
__device__ __forceinline__ uint32_t h2(float x, float y) {
    __half2 h = __floats2half2_rn(x, y);
    return *(uint32_t*)&h;
}
// exp2 of a float pair, computed in f16x2 (1 cvt + 1 MUFU for 2 elements)
__device__ __forceinline__ uint32_t ex2h2(float x, float y) {
    uint32_t p = h2(x, y), r;
    asm("ex2.approx.f16x2 %0, %1;" : "=r"(r) : "r"(p));
    return r;
}
// hardware tanh (MUFU), final-output use only
__device__ __forceinline__ float tanh_ap(float x) {
    float r; asm("tanh.approx.f32 %0, %1;" : "=f"(r) : "f"(x)); return r;
}
__device__ __forceinline__ uint32_t smem_u32(const void* p) {
    return (uint32_t)__cvta_generic_to_shared(p);
}
__device__ __forceinline__ void ldmx4(uint32_t* r, uint32_t addr) {
    asm volatile("ldmatrix.sync.aligned.m8n8.x4.shared.b16 {%0,%1,%2,%3}, [%4];"
        : "=r"(r[0]), "=r"(r[1]), "=r"(r[2]), "=r"(r[3]) : "r"(addr));
}
__device__ __forceinline__ void ldmx4t(uint32_t* r, uint32_t addr) {
    asm volatile("ldmatrix.sync.aligned.m8n8.x4.trans.shared.b16 {%0,%1,%2,%3}, [%4];"
        : "=r"(r[0]), "=r"(r[1]), "=r"(r[2]), "=r"(r[3]) : "r"(addr));
}
__device__ __forceinline__ void cpasync16(uint32_t dst, const void* src) {
    asm volatile("cp.async.cg.shared.global [%0], [%1], 16;" :: "r"(dst), "l"(src));
}
__device__ __forceinline__ void cpasync_commit() {
    asm volatile("cp.async.commit_group;");
}

// ---------------------------------------------------------------------------
// fp32 -> fp16 conversion of x, Wq, Wk, Wv (8 elems/thread — best-known)
// ---------------------------------------------------------------------------
__global__ __launch_bounds__(256) void cvt_fp16(
    const float* __restrict__ x,  const float* __restrict__ Wq,
    const float* __restrict__ Wk, const float* __restrict__ Wv)
{
    size_t i = ((size_t)blockIdx.x * 256 + threadIdx.x) * 8;
    const float* src;
    __half* dst;
    if (i < XN) { src = x + i; dst = g_xh + i; }
    else {
        size_t j = i - XN;
        size_t which = j / WN;
        src = ((which == 0) ? Wq : (which == 1) ? Wk : Wv) + (j - which * WN);
        dst = g_wh + j;
    }
    float4 f0 = *(const float4*)src;
    float4 f1 = *(const float4*)(src + 4);
    uint32_t o[4];
    o[0] = h2(f0.x, f0.y); o[1] = h2(f0.z, f0.w);
    o[2] = h2(f1.x, f1.y); o[3] = h2(f1.z, f1.w);
    *(uint4*)dst = *(uint4*)o;
}

// ---------------------------------------------------------------------------
// QKV GEMM: fp16, 3-stage cp.async ring, XOR-swizzled smem, one sync per
// slab, deferred cp.async after ks=0. BM=BN=128, BK=64, 256 thr, 2 CTAs/SM.
// NEW: smem-staged epilogue -> coalesced STG.128 head-split stores.
// ---------------------------------------------------------------------------
#define GROW 64
#define GEMM_SMEM (6 * 128 * GROW * 2)   // 98304 B (3 stages x A,B)
#define EPS 72   // epilogue smem row stride (halfs)

__global__ __launch_bounds__(256, 2) void qkv_fp16(
    const float* __restrict__ bq, const float* __restrict__ bk,
    const float* __restrict__ bv)
{
    extern __shared__ __half smem[];

    const int which = blockIdx.z;
    const float* bias = (which == 0) ? bq : (which == 1) ? bk : bv;
    __half* out       = (which == 0) ? g_q : (which == 1) ? g_k : g_v;
    const __half* Wh  = g_wh + (size_t)which * WN;

    const int tid = threadIdx.x, lane = tid & 31, warp = tid >> 5;
    const int wm = warp >> 1, wn = warp & 1;
    const int gid = lane >> 2, tig = lane & 3;
    const int m0 = blockIdx.y * 128, n0 = blockIdx.x * 128;

    const int a_r = ((lane >> 3) & 1) * 8 + (lane & 7);
    const int a_ch = lane >> 4;
    const int b_r = lane & 7;
    const int b_j = lane >> 4;
    const int b_ch = (lane >> 3) & 1;

    int crow[4], cch[4];
    #pragma unroll
    for (int t = 0; t < 4; t++) {
        int idx = tid + t * 256;
        crow[t] = idx >> 3;
        cch[t]  = idx & 7;
    }

    auto issue = [&](int slab, int buf) {
        const int k0 = slab * 64;
        __half* dA = smem + (size_t)buf * 128 * GROW;
        __half* dB = smem + (size_t)(3 + buf) * 128 * GROW;
        #pragma unroll
        for (int t = 0; t < 4; t++) {
            int sw = (cch[t] ^ (crow[t] & 7)) * 8;
            cpasync16(smem_u32(&dA[crow[t] * GROW + sw]),
                      &g_xh[(size_t)(m0 + crow[t]) * H_ + k0 + cch[t] * 8]);
            cpasync16(smem_u32(&dB[crow[t] * GROW + sw]),
                      &Wh[(size_t)(n0 + crow[t]) * H_ + k0 + cch[t] * 8]);
        }
        cpasync_commit();
    };

    float c[2][8][4] = {};

    issue(0, 0);
    issue(1, 1);

    #pragma unroll 1
    for (int ot = 0; ot < 4; ot++) {
        #pragma unroll
        for (int sub = 0; sub < 3; sub++) {
            const int it = ot * 3 + sub;
            if (it < 11) asm volatile("cp.async.wait_group 1;");
            else         asm volatile("cp.async.wait_group 0;");
            __syncthreads();

            const __half* cA = smem + (size_t)sub * 128 * GROW;
            const __half* cB = smem + (size_t)(3 + sub) * 128 * GROW;

            #pragma unroll
            for (int ks = 0; ks < 4; ks++) {
                uint32_t af[2][4];
                #pragma unroll
                for (int mt = 0; mt < 2; mt++) {
                    int r = wm * 32 + mt * 16 + a_r;
                    int ch = ks * 2 + a_ch;
                    ldmx4(af[mt], smem_u32(&cA[r * GROW + ((ch ^ (r & 7)) << 3)]));
                }
                uint32_t bf[8][2];
                #pragma unroll
                for (int j = 0; j < 8; j += 2) {
                    int r = wn * 64 + (j + b_j) * 8 + b_r;
                    int ch = ks * 2 + b_ch;
                    uint32_t t[4];
                    ldmx4(t, smem_u32(&cB[r * GROW + ((ch ^ (r & 7)) << 3)]));
                    bf[j][0] = t[0]; bf[j][1] = t[1];
                    bf[j+1][0] = t[2]; bf[j+1][1] = t[3];
                }
                #pragma unroll
                for (int mt = 0; mt < 2; mt++)
                    #pragma unroll
                    for (int j = 0; j < 8; j++)
                        mma_f16(c[mt][j], af[mt], bf[j]);

                // deferred cp.async issue: after the ks=0 ldmatrix burst, the
                // LSU is free while the MMA-heavy ks=1..3 phase runs.
                if (ks == 0 && it + 2 < 12) issue(it + 2, (sub + 2) % 3);
            }
        }
    }

    // ---- smem-staged epilogue: bias+scale, stage warp tile, STG.128 ----
    __syncthreads();                      // ring fully consumed by all warps
    const float scale = (which == 0) ? QSCALE : 1.0f;
    __half* ep = smem + (size_t)warp * (32 * EPS);

    #pragma unroll
    for (int j = 0; j < 8; j++) {
        int colb = j * 8 + 2 * tig;       // 0..63 within the warp's head
        int ncol = n0 + wn * 64 + colb;
        float bs0 = bias[ncol], bs1 = bias[ncol + 1];
        #pragma unroll
        for (int mt = 0; mt < 2; mt++)
            #pragma unroll
            for (int hf = 0; hf < 2; hf++) {
                int r = mt * 16 + hf * 8 + gid;
                *(__half2*)&ep[r * EPS + colb] =
                    __floats2half2_rn((c[mt][j][hf*2+0] + bs0) * scale,
                                      (c[mt][j][hf*2+1] + bs1) * scale);
            }
    }
    __syncwarp();

    const int hh = (n0 + wn * 64) >> 6;   // warp's head (64-col aligned)
    #pragma unroll
    for (int i = 0; i < 8; i++) {
        int idx = lane + i * 32;          // 0..255
        int r = idx >> 3, ck = (idx & 7) * 8;
        int m = m0 + wm * 32 + r;
        int b = m >> 9, s = m & 511;
        *(uint4*)&out[(((size_t)b * NH_ + hh) * S_ + s) * DH_ + ck] =
            *(const uint4*)&ep[r * EPS + ck];
    }
}

// ---------------------------------------------------------------------------
// Flash attention: fp16 HMMA, 256 thr = 8 warps, 128 q/block, 128-key staged
// tiles (two 64-key subtiles). ks-outer S-phase, separate ex2 block, ones-MMA
// row sums, tanh.approx. NEW: smem-staged epilogue -> coalesced STG.128.
// Staging region = Qs+Kb[0] (not touched during final kt=3 iteration).
// ---------------------------------------------------------------------------
#define AKS 72
#define ATTN_SMEM (5 * 128 * AKS * 2)   // Q + 2xK(128) + 2xV(128) = 92160 B
#define OEPS 72   // attn epilogue smem row stride (floats)

__global__ __launch_bounds__(256, 2) void attn_flash(float* __restrict__ out)
{
    extern __shared__ __half asm_[];
    __half* Qs    = asm_;
    __half* Kb[2] = { asm_ + 128*AKS,  asm_ + 2*128*AKS };
    __half* Vb[2] = { asm_ + 3*128*AKS, asm_ + 4*128*AKS };

    const int tid = threadIdx.x, lane = tid & 31, warp = tid >> 5;
    const int gid = lane >> 2, tig = lane & 3;
    const int qt = blockIdx.x, bh = blockIdx.y;
    const int s0 = qt * 128;
    const size_t base = (size_t)bh * S_ * DH_;

    int crow[4], cdg[4];
    #pragma unroll
    for (int t = 0; t < 4; t++) {
        int idx = tid + t * 256;
        crow[t] = idx >> 3;
        cdg[t]  = (idx & 7) * 8;
    }

    auto stage_kv = [&](int ktile, int buf) {
        const size_t gb = base + (size_t)ktile * 128 * DH_;
        #pragma unroll
        for (int t = 0; t < 4; t++) {
            cpasync16(smem_u32(&Kb[buf][crow[t] * AKS + cdg[t]]),
                      &g_k[gb + (size_t)crow[t] * DH_ + cdg[t]]);
            cpasync16(smem_u32(&Vb[buf][crow[t] * AKS + cdg[t]]),
                      &g_v[gb + (size_t)crow[t] * DH_ + cdg[t]]);
        }
        cpasync_commit();
    };

    #pragma unroll
    for (int t = 0; t < 4; t++) {
        cpasync16(smem_u32(&Qs[crow[t] * AKS + cdg[t]]),
                  &g_q[base + (size_t)(s0 + crow[t]) * DH_ + cdg[t]]);
    }
    stage_kv(0, 0);
    asm volatile("cp.async.wait_group 0;");
    __syncthreads();

    const int a_r = ((lane >> 3) & 1) * 8 + (lane & 7);
    const int a_c = (lane >> 4) * 8;
    const int k_r = lane & 7;
    const int k_j = lane >> 4;
    const int k_c = ((lane >> 3) & 1) * 8;
    const int v_r = ((lane >> 3) & 1) * 8 + (lane & 7);
    const int v_j = lane >> 4;

    uint32_t qa[4][4];
    #pragma unroll
    for (int ks = 0; ks < 4; ks++)
        ldmx4(qa[ks], smem_u32(&Qs[(warp * 16 + a_r) * AKS + ks * 16 + a_c]));

    float oc[8][4] = {};
    float lsum[4] = {};                   // ones-MMA row-sum accumulator
    const uint32_t ones[2] = { ONES_H2, ONES_H2 };

    #pragma unroll 1
    for (int kt = 0; kt < 4; kt++) {
        #pragma unroll
        for (int half = 0; half < 2; half++) {
            const __half* cK = Kb[kt & 1] + half * 64 * AKS;
            const __half* cV = Vb[kt & 1] + half * 64 * AKS;

            // ---- S(log2) = Q K^T : ks OUTER, batched K-fragment loads ----
            float sc[8][4] = {};
            #pragma unroll
            for (int ks = 0; ks < 4; ks++) {
                uint32_t kb[4][4];
                #pragma unroll
                for (int jp = 0; jp < 4; jp++)
                    ldmx4(kb[jp],
                        smem_u32(&cK[((2*jp + k_j) * 8 + k_r) * AKS + ks * 16 + k_c]));
                #pragma unroll
                for (int jp = 0; jp < 4; jp++) {
                    mma_f16(sc[2*jp],     qa[ks], kb[jp] + 0);
                    mma_f16(sc[2*jp + 1], qa[ks], kb[jp] + 2);
                }
            }

            // deferred next-tile staging: after the K-ldmatrix bursts, the LSU
            // is free while exp + P@V (MMA-heavy) run.
            if (half == 0 && kt < 3) stage_kv(kt + 1, (kt + 1) & 1);

            // ---- P = ex2(S) directly in f16x2 (separate block: max ILP) ----
            uint32_t plo[8], phi[8];
            #pragma unroll
            for (int j = 0; j < 8; j++) {
                plo[j] = ex2h2(sc[j][0], sc[j][1]);
                phi[j] = ex2h2(sc[j][2], sc[j][3]);
            }

            // ---- O += P V ; row sums += P @ 1 (batched V-fragment loads) ----
            #pragma unroll
            for (int ks = 0; ks < 4; ks++) {
                uint32_t pf[4] = { plo[2*ks], phi[2*ks], plo[2*ks+1], phi[2*ks+1] };
                uint32_t vb[4][4];
                #pragma unroll
                for (int jp = 0; jp < 4; jp++)
                    ldmx4t(vb[jp],
                        smem_u32(&cV[(ks * 16 + v_r) * AKS + (2*jp + v_j) * 8]));
                mma_f16(lsum, pf, ones);
                #pragma unroll
                for (int jp = 0; jp < 4; jp++) {
                    mma_f16(oc[2*jp],     pf, vb[jp] + 0);
                    mma_f16(oc[2*jp + 1], pf, vb[jp] + 2);
                }
            }
        }

        if (kt < 3) {
            asm volatile("cp.async.wait_group 0;");
            __syncthreads();
        }
    }

    const float inv0 = 1.0f / lsum[0];   // row gid   (replicated over columns)
    const float inv1 = 1.0f / lsum[2];   // row gid+8

    // ---- smem-staged epilogue into Qs+Kb[0] region (free during kt=3) ----
    // warp tile: 16 rows x 64 d, staged fp32 stride OEPS, then STG.128.
    float* ep = (float*)asm_ + (size_t)warp * (16 * OEPS);

    #pragma unroll
    for (int j = 0; j < 8; j++) {
        int d = j * 8 + 2 * tig;
        *(float2*)&ep[gid * OEPS + d] =
            make_float2(tanh_ap(oc[j][0] * inv0), tanh_ap(oc[j][1] * inv0));
        *(float2*)&ep[(gid + 8) * OEPS + d] =
            make_float2(tanh_ap(oc[j][2] * inv1), tanh_ap(oc[j][3] * inv1));
    }
    __syncwarp();

    const int b = bh / NH_, h = bh % NH_;
    #pragma unroll
    for (int i = 0; i < 8; i++) {
        int idx = lane + i * 32;          // 0..255
        int r = idx >> 4, ck = (idx & 15) * 4;
        int s = s0 + warp * 16 + r;
        *(uint4*)&out[((size_t)(b * S_ + s)) * H_ + h * DH_ + ck] =
            *(const uint4*)&ep[r * OEPS + ck];
    }
}

// ---------------------------------------------------------------------------
extern "C" void kernel_launch(void* const* d_in, const int* in_sizes, int n_in,
                              void* d_out, int out_size)
{
    const float* x  = (const float*)d_in[0];
    const float* Wq = (const float*)d_in[1];
    const float* bq = (const float*)d_in[2];
    const float* Wk = (const float*)d_in[3];
    const float* bk = (const float*)d_in[4];
    const float* Wv = (const float*)d_in[5];
    const float* bv = (const float*)d_in[6];
    float* out = (float*)d_out;

    cudaFuncSetAttribute(qkv_fp16,
                         cudaFuncAttributeMaxDynamicSharedMemorySize, GEMM_SMEM);
    cudaFuncSetAttribute(attn_flash,
                         cudaFuncAttributeMaxDynamicSharedMemorySize, ATTN_SMEM);

    const int cvt_blocks = (int)((XN + 3 * WN) / (256 * 8));   // 7008
    cvt_fp16<<<cvt_blocks, 256>>>(x, Wq, Wk, Wv);

    dim3 ggrid(H_ / 128, M_ / 128, 3);   // (6, 128, 3)
    qkv_fp16<<<ggrid, 256, GEMM_SMEM>>>(bq, bk, bv);

    dim3 agrid(S_ / 128, B_ * NH_);      // (4, 384)
    attn_flash<<<agrid, 256, ATTN_SMEM>>>(out);
}